// round 9
// baseline (speedup 1.0000x reference)
#include <cuda_runtime.h>
#include <math.h>

// Spectral solution of 1000 masked-Jacobi steps on 512x512, ONE persistent
// kernel:  out_int = S^T * ( W ⊙ (S * B * S^T) ) * S
// B = interior of one exact stencil step of x0 (step 1 reads unmasked x0
// boundary), W = (2/511)^2 * lam^999. Only 128 modes/dim survive lam^999:
// I(m)=m+1 (m<64), m+383 (else).
// Round 9: 256 CTAs / 2 per SM (16 warps/SM) via __launch_bounds__(256,2);
// every stage = 256 one-CTA jobs with the SAME per-thread FMA:LDS ratios:
//  G1: P_h = B*ST          32 tiles(64x32,TM4TN2) x splitK8
//  G2: Cq_h = S*(sum P)    16 tiles(32x32,TM2TN2) x splitK16, B-fuse8
//  G3: U_h = ((sumCq)#W)*S 64 tiles(32x32,TM2TN2) x splitK4,  A-fuse16
//  G4: out = ST*(sum U)   256 tiles(32x32,TM2TN2) full-K, B-fuse4 + shift
// Stage A/B fused per-CTA in smem (2 B rows from 4 local x0 rows).
// Barrier epochs continue across graph replays (base read from release word).

#define NCTA 256
#define TPB  256
#define GT   (NCTA * TPB)
#define SMS  68                  // smem row stride: 272B = 17*16B
#define CHUNK (16 * SMS)

__device__ float g_B [512 * 512];       // stencil(x0) interior, zero padded
__device__ float g_S [128 * 512];       // S[m][c], ld 512 (cols>=510 zero)
__device__ float g_ST[512 * 128];       // ST[k][m], ld 128 (rows>=510 zero)
__device__ float g_P [8 * 512 * 128];   // G1 K-partials
__device__ float g_Cq[16 * 128 * 128];  // G2 K-partials
__device__ float g_U [4 * 128 * 512];   // G3 K-partials
__device__ float g_W [128 * 128];       // spectral weights
__device__ unsigned g_bar[NCTA + 1];

__device__ __forceinline__ unsigned ld_acq(const unsigned* p) {
    unsigned v;
    asm volatile("ld.acquire.gpu.u32 %0, [%1];" : "=r"(v) : "l"(p) : "memory");
    return v;
}
__device__ __forceinline__ void st_rel(unsigned* p, unsigned v) {
    asm volatile("st.release.gpu.u32 [%0], %1;" :: "l"(p), "r"(v) : "memory");
}
__device__ __forceinline__ int modeI(int m) { return (m < 64) ? (m + 1) : (m + 383); }

__device__ __forceinline__ void grid_bar(unsigned ep) {
    __syncthreads();
    const int cta = blockIdx.x, tid = threadIdx.x;
    if (cta == 0) {
        if (tid > 0 && tid < NCTA)
            while (ld_acq(&g_bar[tid]) < ep) { }
        __syncthreads();
        if (tid == 0) st_rel(&g_bar[NCTA], ep);
    } else {
        if (tid == 0) {
            st_rel(&g_bar[cta], ep);
            while (ld_acq(&g_bar[NCTA]) < ep) { }
        }
        __syncthreads();
    }
}

#define GF_AFUSE16 1   // A = (Cq0+..+Cq15) ⊙ W  (lda=128, slab stride 16384)
#define GF_BFUSE8  2   // B = P0+..+P7            (slab stride 65536)
#define GF_BFUSE4  4   // B = U0+..+U3            (slab stride 65536)
#define GF_SHIFT   8   // store out[(r+1)][(c+1)], r,c<510

// One BMxBN tile, 256 threads (16x16 grid), TMxTN acc, BK=16,
// double-buffered smem, ONE __syncthreads per chunk.
template<int BM, int BN, int TM, int TN, int F>
__device__ void gemm_tile(const float* __restrict__ A, int lda,
                          const float* __restrict__ Bop, int ldb,
                          float* __restrict__ Cout, int ldc,
                          int mT, int nT, int kbase, int Klen,
                          float* __restrict__ As, float* __restrict__ Bs) {
    const int tid = threadIdx.x;
    const int tx = tid & 15, ty = tid >> 4;
    // A loader: BM=64 -> float4 per thread; BM=32 -> float2
    const int am = (BM == 64) ? (tid >> 2) : (tid >> 3);
    const int ak = (BM == 64) ? (tid & 3) * 4 : (tid & 7) * 2;
    // B loader: 16 k-rows; BN=64 -> float4; BN=32 -> float2
    const int bk = tid >> 4;
    const int bn = (BN == 64) ? (tid & 15) * 4 : (tid & 15) * 2;

    float4 ra, rb;
    auto loadA = [&](int k0) {
        const int k = kbase + k0 + ak;
        if (F & GF_AFUSE16) {                      // BM==32 path
            const float* p = A + (mT + am) * 128 + k;
            float2 s = *(const float2*)p;
#pragma unroll
            for (int h = 1; h < 16; h++) {
                float2 c = *(const float2*)(p + h * 16384);
                s.x += c.x; s.y += c.y;
            }
            float2 w = *(const float2*)&g_W[(mT + am) * 128 + k];
            ra.x = s.x * w.x; ra.y = s.y * w.y;
        } else if (BM == 64) {
            ra = *(const float4*)(A + (size_t)(mT + am) * lda + k);
        } else {
            float2 v = *(const float2*)(A + (size_t)(mT + am) * lda + k);
            ra.x = v.x; ra.y = v.y;
        }
    };
    auto loadB = [&](int k0) {
        const int k = kbase + k0 + bk;
        const float* p = Bop + (size_t)k * ldb + nT + bn;
        if (F & GF_BFUSE8) {
            float2 s = *(const float2*)p;
#pragma unroll
            for (int h = 1; h < 8; h++) {
                float2 c = *(const float2*)(p + h * 65536);
                s.x += c.x; s.y += c.y;
            }
            rb.x = s.x; rb.y = s.y;
        } else if (F & GF_BFUSE4) {
            float2 s = *(const float2*)p;
#pragma unroll
            for (int h = 1; h < 4; h++) {
                float2 c = *(const float2*)(p + h * 65536);
                s.x += c.x; s.y += c.y;
            }
            rb.x = s.x; rb.y = s.y;
        } else if (BN == 64) {
            rb = *(const float4*)p;
        } else {
            float2 v = *(const float2*)p;
            rb.x = v.x; rb.y = v.y;
        }
    };
    auto stash = [&](int buf) {
        float* as = As + buf * CHUNK;
        float* bs = Bs + buf * CHUNK;
        as[(ak + 0) * SMS + am] = ra.x;            // A transposed
        as[(ak + 1) * SMS + am] = ra.y;
        if (BM == 64) {
            as[(ak + 2) * SMS + am] = ra.z;
            as[(ak + 3) * SMS + am] = ra.w;
        }
        if (BN == 64) *(float4*)&bs[bk * SMS + bn] = rb;
        else          *(float2*)&bs[bk * SMS + bn] = make_float2(rb.x, rb.y);
    };

    float acc[TM][TN];
#pragma unroll
    for (int i = 0; i < TM; i++)
#pragma unroll
        for (int j = 0; j < TN; j++) acc[i][j] = 0.0f;

    const int nchunk = Klen / 16;
    loadA(0); loadB(0);
    stash(0);
    __syncthreads();

    for (int c = 0; c < nchunk; c++) {
        const float* as = As + (c & 1) * CHUNK;
        const float* bs = Bs + (c & 1) * CHUNK;
        if (c + 1 < nchunk) { loadA((c + 1) * 16); loadB((c + 1) * 16); }
#pragma unroll
        for (int kk = 0; kk < 16; kk++) {
            float a[TM], b[TN];
            if (TM == 4) {
                float4 v = *(const float4*)&as[kk * SMS + ty * 4];
                a[0] = v.x; a[1] = v.y; a[2] = v.z; a[3] = v.w;
            } else {
                float2 v = *(const float2*)&as[kk * SMS + ty * 2];
                a[0] = v.x; a[1] = v.y;
            }
            if (TN == 4) {
                float4 v = *(const float4*)&bs[kk * SMS + tx * 4];
                b[0] = v.x; b[1] = v.y; b[2] = v.z; b[3] = v.w;
            } else {
                float2 v = *(const float2*)&bs[kk * SMS + tx * 2];
                b[0] = v.x; b[1] = v.y;
            }
#pragma unroll
            for (int i = 0; i < TM; i++)
#pragma unroll
                for (int j = 0; j < TN; j++) acc[i][j] += a[i] * b[j];
        }
        if (c + 1 < nchunk) stash((c + 1) & 1);    // other buffer: safe
        __syncthreads();
    }

    if (F & GF_SHIFT) {
#pragma unroll
        for (int i = 0; i < TM; i++) {
            int r = mT + ty * TM + i;
            if (r >= 510) continue;
#pragma unroll
            for (int j = 0; j < TN; j++) {
                int c2 = nT + tx * TN + j;
                if (c2 < 510) Cout[(r + 1) * 512 + c2 + 1] = acc[i][j];
            }
        }
    } else {
#pragma unroll
        for (int i = 0; i < TM; i++) {
            float* p = Cout + (size_t)(mT + ty * TM + i) * ldc + nT + tx * TN;
            if (TN == 4) *(float4*)p = make_float4(acc[i][0], acc[i][1], acc[i][2], acc[i][3]);
            else         *(float2*)p = make_float2(acc[i][0], acc[i][1]);
        }
    }
}

__global__ void __launch_bounds__(TPB, 2)
jacobi_fused(const float* __restrict__ X, const float* __restrict__ Y,
             float* __restrict__ out) {
    __shared__ float sx0[4 * 512];                 // local x0 rows (8KB)
    __shared__ float As[2 * CHUNK];
    __shared__ float Bs[2 * CHUNK];
    const int cta = blockIdx.x, tid = threadIdx.x;
    const int gtid = cta * TPB + tid;
    const unsigned eb = __ldcg(&g_bar[NCTA]);

    // ---- Stage A+B fused: 2 B rows per CTA from 4 local x0 rows ----
    const int r0 = cta * 2;
    int nrows = 512 - r0; if (nrows > 4) nrows = 4;
    for (int i = tid; i < nrows * 512; i += TPB) {
        int lr = i >> 9, j = i & 511;
        int g = (r0 + lr) * 512 + j;
        float dx = X[g] - 0.5f, dy = Y[g] - 0.5f;
        sx0[i] = expf(-50.0f * (dx * dx + dy * dy));
    }
    __syncthreads();
    for (int i = tid; i < 2 * 512; i += TPB) {
        int lk = i >> 9, j = i & 511;
        int k = r0 + lk;
        float v = 0.0f;
        if (k < 510 && j < 510)
            v = 0.25f * (((sx0[lk * 512 + j + 1] + sx0[(lk + 2) * 512 + j + 1])
                          + sx0[(lk + 1) * 512 + j]) + sx0[(lk + 1) * 512 + j + 2]);
        g_B[k * 512 + j] = v;
    }
    // sine basis, W, out boundary (grid-strided over 65536 threads)
    for (int i = gtid; i < 512 * 128; i += GT) {
        int k = i >> 7, m = i & 127;
        float v = 0.0f;
        if (k < 510) {
            int a = (modeI(m) * (k + 1)) % 1022;    // exact reduction
            v = sinpif((float)a * (1.0f / 511.0f));
        }
        g_ST[i] = v;
    }
    for (int i = gtid; i < 128 * 512; i += GT) {
        int m = i >> 9, c = i & 511;
        float v = 0.0f;
        if (c < 510) {
            int a = (modeI(m) * (c + 1)) % 1022;
            v = sinpif((float)a * (1.0f / 511.0f));
        }
        g_S[i] = v;
    }
    if (gtid < 128 * 128) {
        int m = gtid >> 7, n = gtid & 127;
        double lam = 0.5 * (cospi((double)modeI(m) / 511.0)
                          + cospi((double)modeI(n) / 511.0));
        double r = 1.0, b = lam; int e = 999;
        while (e) { if (e & 1) r *= b; b *= b; e >>= 1; }
        g_W[gtid] = (float)(r * (4.0 / (511.0 * 511.0)));
    }
    if (gtid < 2048) {
        int e = gtid >> 9, t = gtid & 511;
        if      (e == 0) out[t] = 0.0f;
        else if (e == 1) out[511 * 512 + t] = 0.0f;
        else if (e == 2) out[t * 512] = 0.0f;
        else             out[t * 512 + 511] = 0.0f;
    }
    grid_bar(eb + 1);

    // ---- G1: P_h = B * S^T, 32 tiles(64x32) x splitK8 ----
    {
        int t = cta >> 3, h = cta & 7;             // t:0..31, h:0..7
        gemm_tile<64, 32, 4, 2, 0>(g_B, 512, g_ST, 128,
                                   g_P + h * 65536, 128,
                                   (t >> 2) * 64, (t & 3) * 32, h * 64, 64, As, Bs);
    }
    grid_bar(eb + 2);

    // ---- G2: Cq_h = S * (sum P), 16 tiles(32x32) x splitK16, B-fuse8 ----
    {
        int t = cta >> 4, h = cta & 15;            // t:0..15, h:0..15
        gemm_tile<32, 32, 2, 2, GF_BFUSE8>(g_S, 512, g_P, 128,
                                           g_Cq + h * 16384, 128,
                                           (t >> 2) * 32, (t & 3) * 32, h * 32, 32, As, Bs);
    }
    grid_bar(eb + 3);

    // ---- G3: U_h = ((sum Cq) ⊙ W) * S, 64 tiles(32x32) x splitK4, A-fuse16 ----
    {
        int t = cta >> 2, h = cta & 3;             // t:0..63, h:0..3
        gemm_tile<32, 32, 2, 2, GF_AFUSE16>(g_Cq, 128, g_S, 512,
                                            g_U + h * 65536, 512,
                                            (t >> 4) * 32, (t & 15) * 32, h * 32, 32, As, Bs);
    }
    grid_bar(eb + 4);

    // ---- G4: out = S^T * (U0+..+U3), 256 tiles(32x32), shifted store ----
    {
        gemm_tile<32, 32, 2, 2, GF_BFUSE4 | GF_SHIFT>(g_ST, 128, g_U, 512,
                                                      out, 512,
                                                      (cta >> 4) * 32, (cta & 15) * 32,
                                                      0, 128, As, Bs);
    }
}

extern "C" void kernel_launch(void* const* d_in, const int* in_sizes, int n_in,
                              void* d_out, int out_size) {
    (void)in_sizes; (void)n_in; (void)out_size;
    jacobi_fused<<<NCTA, TPB>>>((const float*)d_in[0], (const float*)d_in[1],
                                (float*)d_out);
}

// round 10
// speedup vs baseline: 1.0940x; 1.0940x over previous
#include <cuda_runtime.h>
#include <math.h>

// Spectral solution of 1000 masked-Jacobi steps on 512x512, ONE persistent
// kernel:  out_int = S^T * ( W ⊙ (S * B * S^T) ) * S
// B = interior of one exact stencil step of x0, W = (2/511)^2 * lam^999,
// lam = (cos(pi I(m)/511)+cos(pi I(n)/511))/2; 128 surviving modes/dim:
// I(m)=m+1 (m<64), m+383 (else).
// Round 10: KILL FP64 IN THE HOT PATH. Blackwell Ultra fp64 is ~18 cyc/op —
// the old W loop (2 fp64 cospi + 18 DMUL per entry x 16K entries) was ~25-30us
// per SM, dominating the whole kernel. Now: 128 fp64 cospi TOTAL (one thread
// each) -> double-single (hi,lo) seeds; W powering done in DS fp32 (Dekker
// two-sum + FMA-based DS mul), ~150 fp32 ops/entry, <1us chip-wide.
// Everything else identical to round 8 (33.2us config).

#define NCTA 128
#define TPB  256
#define GT   (NCTA * TPB)
#define SMS  68                  // smem row stride: 272B = 17*16B
#define CHUNK (16 * SMS)

__device__ float g_B [512 * 512];      // stencil(x0) interior, zero padded
__device__ float g_S [128 * 512];      // S[m][c], ld 512 (cols>=510 zero)
__device__ float g_ST[512 * 128];      // ST[k][m], ld 128 (rows>=510 zero)
__device__ float g_P [8 * 512 * 128];  // G1 K-partials
__device__ float g_Cq[8 * 128 * 128];  // G2 K-partials
__device__ float g_U [2 * 128 * 512];  // G3 K-partials
__device__ float g_W [128 * 128];      // spectral weights
__device__ float2 g_cds[128];          // cos(pi*I(m)/511) as double-single
__device__ unsigned g_bar[NCTA + 1];

__device__ __forceinline__ unsigned ld_acq(const unsigned* p) {
    unsigned v;
    asm volatile("ld.acquire.gpu.u32 %0, [%1];" : "=r"(v) : "l"(p) : "memory");
    return v;
}
__device__ __forceinline__ void st_rel(unsigned* p, unsigned v) {
    asm volatile("st.release.gpu.u32 [%0], %1;" :: "l"(p), "r"(v) : "memory");
}
__device__ __forceinline__ int modeI(int m) { return (m < 64) ? (m + 1) : (m + 383); }

__device__ __forceinline__ void grid_bar(unsigned ep) {
    __syncthreads();
    const int cta = blockIdx.x, tid = threadIdx.x;
    if (cta == 0) {
        if (tid > 0 && tid < NCTA)
            while (ld_acq(&g_bar[tid]) < ep) { }
        __syncthreads();
        if (tid == 0) st_rel(&g_bar[NCTA], ep);
    } else {
        if (tid == 0) {
            st_rel(&g_bar[cta], ep);
            while (ld_acq(&g_bar[NCTA]) < ep) { }
        }
        __syncthreads();
    }
}

// ---- double-single (two-float) helpers ----
struct DS { float hi, lo; };
__device__ __forceinline__ DS ds_renorm(float s, float e) {
    float hi = s + e;
    float lo = e - (hi - s);
    return DS{hi, lo};
}
__device__ __forceinline__ DS ds_add(DS a, DS b) {          // Knuth two-sum
    float s = a.hi + b.hi;
    float v = s - a.hi;
    float e = (a.hi - (s - v)) + (b.hi - v);
    return ds_renorm(s, (e + a.lo) + b.lo);
}
__device__ __forceinline__ DS ds_mul(DS a, DS b) {          // Dekker w/ FMA
    float p = a.hi * b.hi;
    float e = fmaf(a.hi, b.hi, -p);
    e = fmaf(a.hi, b.lo, e);
    e = fmaf(a.lo, b.hi, e);
    return ds_renorm(p, e);
}

#define GF_AFUSE8 1   // A = (Cq0+..+Cq7) ⊙ W   (lda=128, stride 16384)
#define GF_BFUSE8 2   // B = P0+..+P7           (stride 65536)
#define GF_BFUSE2 4   // B = U0+U1              (stride 65536)
#define GF_SHIFT  8   // store out[(r+1)][(c+1)], r,c<510

// One BMxBN tile, 256 threads (16x16 grid), TMxTN acc, BK=16,
// double-buffered smem, ONE __syncthreads per chunk.
template<int BM, int BN, int TM, int TN, int F>
__device__ void gemm_tile(const float* __restrict__ A, int lda,
                          const float* __restrict__ Bop, int ldb,
                          float* __restrict__ Cout, int ldc,
                          int mT, int nT, int kbase, int Klen,
                          float* __restrict__ As, float* __restrict__ Bs) {
    const int tid = threadIdx.x;
    const int tx = tid & 15, ty = tid >> 4;
    const int am = (BM == 64) ? (tid >> 2) : (tid >> 3);
    const int ak = (BM == 64) ? (tid & 3) * 4 : (tid & 7) * 2;
    const int bk = tid >> 4;
    const int bn = (BN == 64) ? (tid & 15) * 4 : (tid & 15) * 2;

    float4 ra, rb;
    auto loadA = [&](int k0) {
        const int k = kbase + k0 + ak;
        if (F & GF_AFUSE8) {                       // BM==32 path
            const float* p = A + (mT + am) * 128 + k;
            float2 s = *(const float2*)p;
#pragma unroll
            for (int h = 1; h < 8; h++) {
                float2 c = *(const float2*)(p + h * 16384);
                s.x += c.x; s.y += c.y;
            }
            float2 w = *(const float2*)&g_W[(mT + am) * 128 + k];
            ra.x = s.x * w.x; ra.y = s.y * w.y;
        } else if (BM == 64) {
            ra = *(const float4*)(A + (size_t)(mT + am) * lda + k);
        } else {
            float2 v = *(const float2*)(A + (size_t)(mT + am) * lda + k);
            ra.x = v.x; ra.y = v.y;
        }
    };
    auto loadB = [&](int k0) {
        const int k = kbase + k0 + bk;
        const float* p = Bop + (size_t)k * ldb + nT + bn;
        if (F & GF_BFUSE8) {
            float2 s = *(const float2*)p;
#pragma unroll
            for (int h = 1; h < 8; h++) {
                float2 c = *(const float2*)(p + h * 65536);
                s.x += c.x; s.y += c.y;
            }
            rb.x = s.x; rb.y = s.y;
        } else if (F & GF_BFUSE2) {
            float2 u = *(const float2*)p, v = *(const float2*)(p + 65536);
            rb.x = u.x + v.x; rb.y = u.y + v.y;
        } else if (BN == 64) {
            rb = *(const float4*)p;
        } else {
            float2 v = *(const float2*)p;
            rb.x = v.x; rb.y = v.y;
        }
    };
    auto stash = [&](int buf) {
        float* as = As + buf * CHUNK;
        float* bs = Bs + buf * CHUNK;
        as[(ak + 0) * SMS + am] = ra.x;            // A transposed
        as[(ak + 1) * SMS + am] = ra.y;
        if (BM == 64) {
            as[(ak + 2) * SMS + am] = ra.z;
            as[(ak + 3) * SMS + am] = ra.w;
        }
        if (BN == 64) *(float4*)&bs[bk * SMS + bn] = rb;
        else          *(float2*)&bs[bk * SMS + bn] = make_float2(rb.x, rb.y);
    };

    float acc[TM][TN];
#pragma unroll
    for (int i = 0; i < TM; i++)
#pragma unroll
        for (int j = 0; j < TN; j++) acc[i][j] = 0.0f;

    const int nchunk = Klen / 16;
    loadA(0); loadB(0);
    stash(0);
    __syncthreads();

    for (int c = 0; c < nchunk; c++) {
        const float* as = As + (c & 1) * CHUNK;
        const float* bs = Bs + (c & 1) * CHUNK;
        if (c + 1 < nchunk) { loadA((c + 1) * 16); loadB((c + 1) * 16); }
#pragma unroll
        for (int kk = 0; kk < 16; kk++) {
            float a[TM], b[TN];
            if (TM == 4) {
                float4 v = *(const float4*)&as[kk * SMS + ty * 4];
                a[0] = v.x; a[1] = v.y; a[2] = v.z; a[3] = v.w;
            } else {
                float2 v = *(const float2*)&as[kk * SMS + ty * 2];
                a[0] = v.x; a[1] = v.y;
            }
            if (TN == 4) {
                float4 v = *(const float4*)&bs[kk * SMS + tx * 4];
                b[0] = v.x; b[1] = v.y; b[2] = v.z; b[3] = v.w;
            } else {
                float2 v = *(const float2*)&bs[kk * SMS + tx * 2];
                b[0] = v.x; b[1] = v.y;
            }
#pragma unroll
            for (int i = 0; i < TM; i++)
#pragma unroll
                for (int j = 0; j < TN; j++) acc[i][j] += a[i] * b[j];
        }
        if (c + 1 < nchunk) stash((c + 1) & 1);    // other buffer: safe
        __syncthreads();
    }

    if (F & GF_SHIFT) {
#pragma unroll
        for (int i = 0; i < TM; i++) {
            int r = mT + ty * TM + i;
            if (r >= 510) continue;
#pragma unroll
            for (int j = 0; j < TN; j++) {
                int c2 = nT + tx * TN + j;
                if (c2 < 510) Cout[(r + 1) * 512 + c2 + 1] = acc[i][j];
            }
        }
    } else {
#pragma unroll
        for (int i = 0; i < TM; i++) {
            float* p = Cout + (size_t)(mT + ty * TM + i) * ldc + nT + tx * TN;
            if (TN == 4) *(float4*)p = make_float4(acc[i][0], acc[i][1], acc[i][2], acc[i][3]);
            else         *(float2*)p = make_float2(acc[i][0], acc[i][1]);
        }
    }
}

__global__ void __launch_bounds__(TPB, 1)
jacobi_fused(const float* __restrict__ X, const float* __restrict__ Y,
             float* __restrict__ out) {
    __shared__ float sx0[6 * 512];                 // local x0 rows (12KB)
    __shared__ float As[2 * CHUNK];
    __shared__ float Bs[2 * CHUNK];
    const int cta = blockIdx.x, tid = threadIdx.x;
    const int gtid = cta * TPB + tid;
    const unsigned eb = __ldcg(&g_bar[NCTA]);

    // ---- Stage A+B fused ----
    // the ONLY fp64 in the kernel: 128 cospi calls, one thread each
    if (gtid < 128) {
        double c = cospi((double)modeI(gtid) / 511.0);
        float hi = (float)c;
        float lo = (float)(c - (double)hi);
        g_cds[gtid] = make_float2(hi, lo);
    }
    // x0 rows r0..r0+5 locally (only rows this CTA's B rows need)
    const int r0 = cta * 4;
    int nrows = 512 - r0; if (nrows > 6) nrows = 6;
    for (int i = tid; i < nrows * 512; i += TPB) {
        int lr = i >> 9, j = i & 511;
        int g = (r0 + lr) * 512 + j;
        float dx = X[g] - 0.5f, dy = Y[g] - 0.5f;
        sx0[i] = expf(-50.0f * (dx * dx + dy * dy));
    }
    __syncthreads();
    // B rows r0..r0+3: one exact stencil step (zero outside 510x510)
    for (int i = tid; i < 4 * 512; i += TPB) {
        int lk = i >> 9, j = i & 511;
        int k = r0 + lk;
        float v = 0.0f;
        if (k < 510 && j < 510)
            v = 0.25f * (((sx0[lk * 512 + j + 1] + sx0[(lk + 2) * 512 + j + 1])
                          + sx0[(lk + 1) * 512 + j]) + sx0[(lk + 1) * 512 + j + 2]);
        g_B[k * 512 + j] = v;
    }
    // sine basis + out boundary (grid-strided)
    for (int i = gtid; i < 512 * 128; i += GT) {
        int k = i >> 7, m = i & 127;
        float v = 0.0f;
        if (k < 510) {
            int a = (modeI(m) * (k + 1)) % 1022;    // exact reduction
            v = sinpif((float)a * (1.0f / 511.0f));
        }
        g_ST[i] = v;
    }
    for (int i = gtid; i < 128 * 512; i += GT) {
        int m = i >> 9, c = i & 511;
        float v = 0.0f;
        if (c < 510) {
            int a = (modeI(m) * (c + 1)) % 1022;
            v = sinpif((float)a * (1.0f / 511.0f));
        }
        g_S[i] = v;
    }
    for (int i = gtid; i < 2048; i += GT) {
        int e = i >> 9, t = i & 511;
        if      (e == 0) out[t] = 0.0f;
        else if (e == 1) out[511 * 512 + t] = 0.0f;
        else if (e == 2) out[t * 512] = 0.0f;
        else             out[t * 512 + 511] = 0.0f;
    }
    grid_bar(eb + 1);

    // ---- W weights in double-single fp32 (written well before G3 reads:
    //      barriers eb+2 and eb+3 order the visibility) ----
    for (int i = gtid; i < 128 * 128; i += GT) {
        int m = i >> 7, n = i & 127;
        float2 cm = g_cds[m], cn = g_cds[n];
        DS lam = ds_add(DS{cm.x, cm.y}, DS{cn.x, cn.y});
        lam.hi *= 0.5f; lam.lo *= 0.5f;            // exact scale by 2^-1
        DS r{1.0f, 0.0f}, b = lam;
        int e = 999;
        while (e) {                                 // 18 DS multiplies
            if (e & 1) r = ds_mul(r, b);
            b = ds_mul(b, b);
            e >>= 1;
        }
        // scale by 4/511^2 in DS (constant split hi+lo)
        const DS K{1.5318627e-05f, -5.6477107e-13f};
        r = ds_mul(r, K);
        g_W[i] = r.hi + r.lo;
    }

    // ---- G1: P_h = B * S^T, 16 tiles(64x64) x splitK8 ----
    {
        int t = cta >> 3, h = cta & 7;
        gemm_tile<64, 64, 4, 4, 0>(g_B, 512, g_ST, 128,
                                   g_P + h * 65536, 128,
                                   (t >> 1) * 64, (t & 1) * 64, h * 64, 64, As, Bs);
    }
    grid_bar(eb + 2);

    // ---- G2: Cq_h = S * (sum P), 16 tiles(32x32) x splitK8, B-fuse8 ----
    {
        int t = cta >> 3, h = cta & 7;
        gemm_tile<32, 32, 2, 2, GF_BFUSE8>(g_S, 512, g_P, 128,
                                           g_Cq + h * 16384, 128,
                                           (t >> 2) * 32, (t & 3) * 32, h * 64, 64, As, Bs);
    }
    grid_bar(eb + 3);

    // ---- G3: U_h = ((sum Cq) ⊙ W) * S, 64 tiles(32x32) x splitK2, A-fuse ----
    {
        int t = cta >> 1, h = cta & 1;
        gemm_tile<32, 32, 2, 2, GF_AFUSE8>(g_Cq, 128, g_S, 512,
                                           g_U + h * 65536, 512,
                                           (t >> 4) * 32, (t & 15) * 32, h * 64, 64, As, Bs);
    }
    grid_bar(eb + 4);

    // ---- G4: out = S^T * (U0+U1), 128 tiles(64x32), shifted store ----
    {
        gemm_tile<64, 32, 4, 2, GF_BFUSE2 | GF_SHIFT>(g_ST, 128, g_U, 512,
                                                      out, 512,
                                                      (cta >> 4) * 64, (cta & 15) * 32,
                                                      0, 128, As, Bs);
    }
}

extern "C" void kernel_launch(void* const* d_in, const int* in_sizes, int n_in,
                              void* d_out, int out_size) {
    (void)in_sizes; (void)n_in; (void)out_size;
    jacobi_fused<<<NCTA, TPB>>>((const float*)d_in[0], (const float*)d_in[1],
                                (float*)d_out);
}

// round 11
// speedup vs baseline: 1.1505x; 1.0516x over previous
#include <cuda_runtime.h>
#include <math.h>

// Spectral solution of 1000 masked-Jacobi steps on 512x512, ONE persistent
// kernel:  out_int = S^T * ( W ⊙ (S * B * S^T) ) * S
// B = interior of one exact stencil step of x0, W = (2/511)^2 * lam^999;
// 128 surviving modes/dim: I(m)=m+1 (m<64), m+383 (else).
// Round 11: 512 threads/CTA split into TWO independent 256-thread halves,
// each running its own GEMM job with its own smem buffers and NAMED barrier
// (bar.sync 1/2, 256). -> 4 warps/SMSP with per-thread FMA intensity
// UNCHANGED from the 30.6us config. Every stage = 256 jobs (cta*2+half):
//  G1: P_h = B*ST          16 tiles(64x64,4x4) x splitK16
//  G2: Cq_h = S*(sum P)    16 tiles(32x32,2x2) x splitK16, B-fuse16
//  G3: U_h = ((sumCq)#W)*S 64 tiles(32x32,2x2) x splitK4,  A-fuse16
//  G4: out = ST*(sum U)   256 tiles(32x32,2x2) full-K, B-fuse4 + shift
// W weights in double-single fp32 (only 128 fp64 cospi calls total).

#define NCTA 128
#define TPB  512
#define HTPB 256                 // threads per half
#define GT   (NCTA * TPB)
#define SMS  68                  // smem row stride: 272B = 17*16B
#define CHUNK (16 * SMS)

__device__ float g_B [512 * 512];       // stencil(x0) interior, zero padded
__device__ float g_S [128 * 512];       // S[m][c], ld 512 (cols>=510 zero)
__device__ float g_ST[512 * 128];       // ST[k][m], ld 128 (rows>=510 zero)
__device__ float g_P [16 * 512 * 128];  // G1 K-partials (16 slabs)
__device__ float g_Cq[16 * 128 * 128];  // G2 K-partials (16 slabs)
__device__ float g_U [4 * 128 * 512];   // G3 K-partials (4 slabs)
__device__ float g_W [128 * 128];       // spectral weights
__device__ float2 g_cds[128];           // cos(pi*I(m)/511), double-single
__device__ unsigned g_bar[NCTA + 1];

__device__ __forceinline__ unsigned ld_acq(const unsigned* p) {
    unsigned v;
    asm volatile("ld.acquire.gpu.u32 %0, [%1];" : "=r"(v) : "l"(p) : "memory");
    return v;
}
__device__ __forceinline__ void st_rel(unsigned* p, unsigned v) {
    asm volatile("st.release.gpu.u32 [%0], %1;" :: "l"(p), "r"(v) : "memory");
}
__device__ __forceinline__ void bar_named(int id) {
    asm volatile("bar.sync %0, %1;" :: "r"(id), "r"(HTPB) : "memory");
}
__device__ __forceinline__ int modeI(int m) { return (m < 64) ? (m + 1) : (m + 383); }

__device__ __forceinline__ void grid_bar(unsigned ep) {
    __syncthreads();
    const int cta = blockIdx.x, tid = threadIdx.x;
    if (cta == 0) {
        if (tid > 0 && tid < NCTA)
            while (ld_acq(&g_bar[tid]) < ep) { }
        __syncthreads();
        if (tid == 0) st_rel(&g_bar[NCTA], ep);
    } else {
        if (tid == 0) {
            st_rel(&g_bar[cta], ep);
            while (ld_acq(&g_bar[NCTA]) < ep) { }
        }
        __syncthreads();
    }
}

// ---- double-single (two-float) helpers ----
struct DS { float hi, lo; };
__device__ __forceinline__ DS ds_renorm(float s, float e) {
    float hi = s + e;
    float lo = e - (hi - s);
    return DS{hi, lo};
}
__device__ __forceinline__ DS ds_add(DS a, DS b) {          // Knuth two-sum
    float s = a.hi + b.hi;
    float v = s - a.hi;
    float e = (a.hi - (s - v)) + (b.hi - v);
    return ds_renorm(s, (e + a.lo) + b.lo);
}
__device__ __forceinline__ DS ds_mul(DS a, DS b) {          // Dekker w/ FMA
    float p = a.hi * b.hi;
    float e = fmaf(a.hi, b.hi, -p);
    e = fmaf(a.hi, b.lo, e);
    e = fmaf(a.lo, b.hi, e);
    return ds_renorm(p, e);
}

#define GF_AFUSE16 1   // A = (Cq0+..+Cq15) ⊙ W  (lda=128, slab 16384)
#define GF_BFUSE16 2   // B = P0+..+P15           (slab 65536)
#define GF_BFUSE4  4   // B = U0+..+U3            (slab 65536)
#define GF_SHIFT   8   // store out[(r+1)][(c+1)], r,c<510

// One BMxBN tile, HTPB threads (16x16 grid), TMxTN acc, BK=16,
// double-buffered smem, ONE named barrier per chunk. tid is half-local.
template<int BM, int BN, int TM, int TN, int F>
__device__ void gemm_tile(const float* __restrict__ A, int lda,
                          const float* __restrict__ Bop, int ldb,
                          float* __restrict__ Cout, int ldc,
                          int mT, int nT, int kbase, int Klen,
                          int tid, int barid,
                          float* __restrict__ As, float* __restrict__ Bs) {
    const int tx = tid & 15, ty = tid >> 4;
    const int am = (BM == 64) ? (tid >> 2) : (tid >> 3);
    const int ak = (BM == 64) ? (tid & 3) * 4 : (tid & 7) * 2;
    const int bk = tid >> 4;
    const int bn = (BN == 64) ? (tid & 15) * 4 : (tid & 15) * 2;

    float4 ra, rb;
    auto loadA = [&](int k0) {
        const int k = kbase + k0 + ak;
        if (F & GF_AFUSE16) {                      // BM==32 path
            const float* p = A + (mT + am) * 128 + k;
            float2 s = *(const float2*)p;
#pragma unroll
            for (int h = 1; h < 16; h++) {
                float2 c = *(const float2*)(p + h * 16384);
                s.x += c.x; s.y += c.y;
            }
            float2 w = *(const float2*)&g_W[(mT + am) * 128 + k];
            ra.x = s.x * w.x; ra.y = s.y * w.y;
        } else if (BM == 64) {
            ra = *(const float4*)(A + (size_t)(mT + am) * lda + k);
        } else {
            float2 v = *(const float2*)(A + (size_t)(mT + am) * lda + k);
            ra.x = v.x; ra.y = v.y;
        }
    };
    auto loadB = [&](int k0) {
        const int k = kbase + k0 + bk;
        const float* p = Bop + (size_t)k * ldb + nT + bn;
        if (F & GF_BFUSE16) {
            float2 s = *(const float2*)p;
#pragma unroll
            for (int h = 1; h < 16; h++) {
                float2 c = *(const float2*)(p + h * 65536);
                s.x += c.x; s.y += c.y;
            }
            rb.x = s.x; rb.y = s.y;
        } else if (F & GF_BFUSE4) {
            float2 s = *(const float2*)p;
#pragma unroll
            for (int h = 1; h < 4; h++) {
                float2 c = *(const float2*)(p + h * 65536);
                s.x += c.x; s.y += c.y;
            }
            rb.x = s.x; rb.y = s.y;
        } else if (BN == 64) {
            rb = *(const float4*)p;
        } else {
            float2 v = *(const float2*)p;
            rb.x = v.x; rb.y = v.y;
        }
    };
    auto stash = [&](int buf) {
        float* as = As + buf * CHUNK;
        float* bs = Bs + buf * CHUNK;
        as[(ak + 0) * SMS + am] = ra.x;            // A transposed
        as[(ak + 1) * SMS + am] = ra.y;
        if (BM == 64) {
            as[(ak + 2) * SMS + am] = ra.z;
            as[(ak + 3) * SMS + am] = ra.w;
        }
        if (BN == 64) *(float4*)&bs[bk * SMS + bn] = rb;
        else          *(float2*)&bs[bk * SMS + bn] = make_float2(rb.x, rb.y);
    };

    float acc[TM][TN];
#pragma unroll
    for (int i = 0; i < TM; i++)
#pragma unroll
        for (int j = 0; j < TN; j++) acc[i][j] = 0.0f;

    const int nchunk = Klen / 16;
    loadA(0); loadB(0);
    stash(0);
    bar_named(barid);

    for (int c = 0; c < nchunk; c++) {
        const float* as = As + (c & 1) * CHUNK;
        const float* bs = Bs + (c & 1) * CHUNK;
        if (c + 1 < nchunk) { loadA((c + 1) * 16); loadB((c + 1) * 16); }
#pragma unroll
        for (int kk = 0; kk < 16; kk++) {
            float a[TM], b[TN];
            if (TM == 4) {
                float4 v = *(const float4*)&as[kk * SMS + ty * 4];
                a[0] = v.x; a[1] = v.y; a[2] = v.z; a[3] = v.w;
            } else {
                float2 v = *(const float2*)&as[kk * SMS + ty * 2];
                a[0] = v.x; a[1] = v.y;
            }
            if (TN == 4) {
                float4 v = *(const float4*)&bs[kk * SMS + tx * 4];
                b[0] = v.x; b[1] = v.y; b[2] = v.z; b[3] = v.w;
            } else {
                float2 v = *(const float2*)&bs[kk * SMS + tx * 2];
                b[0] = v.x; b[1] = v.y;
            }
#pragma unroll
            for (int i = 0; i < TM; i++)
#pragma unroll
                for (int j = 0; j < TN; j++) acc[i][j] += a[i] * b[j];
        }
        if (c + 1 < nchunk) stash((c + 1) & 1);    // other buffer: safe
        bar_named(barid);
    }

    if (F & GF_SHIFT) {
#pragma unroll
        for (int i = 0; i < TM; i++) {
            int r = mT + ty * TM + i;
            if (r >= 510) continue;
#pragma unroll
            for (int j = 0; j < TN; j++) {
                int c2 = nT + tx * TN + j;
                if (c2 < 510) Cout[(r + 1) * 512 + c2 + 1] = acc[i][j];
            }
        }
    } else {
#pragma unroll
        for (int i = 0; i < TM; i++) {
            float* p = Cout + (size_t)(mT + ty * TM + i) * ldc + nT + tx * TN;
            if (TN == 4) *(float4*)p = make_float4(acc[i][0], acc[i][1], acc[i][2], acc[i][3]);
            else         *(float2*)p = make_float2(acc[i][0], acc[i][1]);
        }
    }
}

__global__ void __launch_bounds__(TPB, 1)
jacobi_fused(const float* __restrict__ X, const float* __restrict__ Y,
             float* __restrict__ out) {
    __shared__ float sx0[6 * 512];                 // 12KB
    __shared__ float As[2 * 2 * CHUNK];            // [half][buf]
    __shared__ float Bs[2 * 2 * CHUNK];
    const int cta = blockIdx.x, tid = threadIdx.x;
    const int gtid = cta * TPB + tid;
    const int half = tid >> 8;                     // warp-aligned split
    const int htid = tid & 255;
    const int barid = 1 + half;
    float* myAs = As + half * 2 * CHUNK;
    float* myBs = Bs + half * 2 * CHUNK;
    const unsigned eb = __ldcg(&g_bar[NCTA]);

    // ---- Stage A+B fused ----
    if (gtid < 128) {                              // ONLY fp64: 128 cospi calls
        double c = cospi((double)modeI(gtid) / 511.0);
        float hi = (float)c;
        float lo = (float)(c - (double)hi);
        g_cds[gtid] = make_float2(hi, lo);
    }
    const int r0 = cta * 4;
    int nrows = 512 - r0; if (nrows > 6) nrows = 6;
    for (int i = tid; i < nrows * 512; i += TPB) {
        int lr = i >> 9, j = i & 511;
        int g = (r0 + lr) * 512 + j;
        float dx = X[g] - 0.5f, dy = Y[g] - 0.5f;
        sx0[i] = expf(-50.0f * (dx * dx + dy * dy));
    }
    __syncthreads();
    for (int i = tid; i < 4 * 512; i += TPB) {     // exact stencil step
        int lk = i >> 9, j = i & 511;
        int k = r0 + lk;
        float v = 0.0f;
        if (k < 510 && j < 510)
            v = 0.25f * (((sx0[lk * 512 + j + 1] + sx0[(lk + 2) * 512 + j + 1])
                          + sx0[(lk + 1) * 512 + j]) + sx0[(lk + 1) * 512 + j + 2]);
        g_B[k * 512 + j] = v;
    }
    for (int i = gtid; i < 512 * 128; i += GT) {   // ST[k][m]
        int k = i >> 7, m = i & 127;
        float v = 0.0f;
        if (k < 510) {
            int a = (modeI(m) * (k + 1)) % 1022;   // exact reduction
            v = sinpif((float)a * (1.0f / 511.0f));
        }
        g_ST[i] = v;
    }
    for (int i = gtid; i < 128 * 512; i += GT) {   // S[m][c]
        int m = i >> 9, c = i & 511;
        float v = 0.0f;
        if (c < 510) {
            int a = (modeI(m) * (c + 1)) % 1022;
            v = sinpif((float)a * (1.0f / 511.0f));
        }
        g_S[i] = v;
    }
    for (int i = gtid; i < 2048; i += GT) {        // out boundary
        int e = i >> 9, t = i & 511;
        if      (e == 0) out[t] = 0.0f;
        else if (e == 1) out[511 * 512 + t] = 0.0f;
        else if (e == 2) out[t * 512] = 0.0f;
        else             out[t * 512 + 511] = 0.0f;
    }
    grid_bar(eb + 1);

    // ---- W weights in double-single fp32 (visible to G3 after eb+2/eb+3) ----
    for (int i = gtid; i < 128 * 128; i += GT) {
        int m = i >> 7, n = i & 127;
        float2 cm = g_cds[m], cn = g_cds[n];
        DS lam = ds_add(DS{cm.x, cm.y}, DS{cn.x, cn.y});
        lam.hi *= 0.5f; lam.lo *= 0.5f;            // exact scale by 2^-1
        DS r{1.0f, 0.0f}, b = lam;
        int e = 999;
        while (e) {
            if (e & 1) r = ds_mul(r, b);
            b = ds_mul(b, b);
            e >>= 1;
        }
        const DS K{1.5318627e-05f, -5.6477107e-13f};   // 4/511^2 split
        r = ds_mul(r, K);
        g_W[i] = r.hi + r.lo;
    }

    const int jid = cta * 2 + half;                // 0..255

    // ---- G1: P_h = B * S^T, 16 tiles(64x64) x splitK16 ----
    {
        int t = jid >> 4, h = jid & 15;
        gemm_tile<64, 64, 4, 4, 0>(g_B, 512, g_ST, 128,
                                   g_P + h * 65536, 128,
                                   (t >> 1) * 64, (t & 1) * 64, h * 32, 32,
                                   htid, barid, myAs, myBs);
    }
    grid_bar(eb + 2);

    // ---- G2: Cq_h = S * (sum P), 16 tiles(32x32) x splitK16, B-fuse16 ----
    {
        int t = jid >> 4, h = jid & 15;
        gemm_tile<32, 32, 2, 2, GF_BFUSE16>(g_S, 512, g_P, 128,
                                            g_Cq + h * 16384, 128,
                                            (t >> 2) * 32, (t & 3) * 32, h * 32, 32,
                                            htid, barid, myAs, myBs);
    }
    grid_bar(eb + 3);

    // ---- G3: U_h = ((sum Cq) ⊙ W) * S, 64 tiles(32x32) x splitK4, A-fuse16 ----
    {
        int t = jid >> 2, h = jid & 3;
        gemm_tile<32, 32, 2, 2, GF_AFUSE16>(g_Cq, 128, g_S, 512,
                                            g_U + h * 65536, 512,
                                            (t >> 4) * 32, (t & 15) * 32, h * 32, 32,
                                            htid, barid, myAs, myBs);
    }
    grid_bar(eb + 4);

    // ---- G4: out = S^T * (U0+..+U3), 256 tiles(32x32), shifted store ----
    {
        gemm_tile<32, 32, 2, 2, GF_BFUSE4 | GF_SHIFT>(g_ST, 128, g_U, 512,
                                                      out, 512,
                                                      (jid >> 4) * 32, (jid & 15) * 32,
                                                      0, 128,
                                                      htid, barid, myAs, myBs);
    }
}

extern "C" void kernel_launch(void* const* d_in, const int* in_sizes, int n_in,
                              void* d_out, int out_size) {
    (void)in_sizes; (void)n_in; (void)out_size;
    jacobi_fused<<<NCTA, TPB>>>((const float*)d_in[0], (const float*)d_in[1],
                                (float*)d_out);
}